// round 4
// baseline (speedup 1.0000x reference)
#include <cuda_runtime.h>
#include <cstdint>

// Problem constants
#define B_   4096
#define T_   128
#define H_   128
#define G_   512   // 4*H
#define M_   32    // batch rows per CTA
#define KC_  32    // K-chunk staged per cp.async round
#define NTHR 512   // 16 warps -> 4 per SMSP (was 8 warps: latency-exposed)

typedef unsigned long long ull_t;

// ---------------- scratch (device globals; no runtime allocation) ----------------
__device__ float g_buf[(size_t)B_ * T_ * H_];    // 256 MB, layers run in-place
__device__ float g_wt[3][256 * G_];              // K-major combined [w_ih | w_hh], zero-padded
__device__ float g_bias[3][G_];                  // b_ih + b_hh

// ---------------- small helpers ----------------
__device__ __forceinline__ float tanha(float x) {
    float r; asm("tanh.approx.f32 %0, %1;" : "=f"(r) : "f"(x)); return r;
}
__device__ __forceinline__ float sigm(float x) {
    return 0.5f * tanha(0.5f * x) + 0.5f;
}

#define FMA2(acc, a, b) asm("fma.rn.f32x2 %0, %1, %2, %3;" : "=l"(acc) : "l"(a), "l"(b), "l"(acc))

__device__ __forceinline__ void cp16(void* smem_dst, const void* gsrc) {
    unsigned sa = (unsigned)__cvta_generic_to_shared(smem_dst);
    asm volatile("cp.async.cg.shared.global [%0], [%1], 16;" :: "r"(sa), "l"(gsrc));
}
#define CP_COMMIT() asm volatile("cp.async.commit_group;")
#define CP_WAIT1()  asm volatile("cp.async.wait_group 1;")

union F2U { float2 f; ull_t u; };

// ---------------- prep: build K-major combined weight + fused bias ----------------
__global__ void prep_kernel(const float* __restrict__ wih, const float* __restrict__ whh,
                            const float* __restrict__ bih, const float* __restrict__ bhh,
                            int layer, int IN) {
    int k = blockIdx.x;          // 0..255
    int c = threadIdx.x;         // 0..511
    int Kpad = ((IN + H_) + KC_ - 1) / KC_ * KC_;
    if (k < Kpad) {
        float v = 0.0f;
        if (k < IN)             v = wih[c * IN + k];
        else if (k < IN + H_)   v = whh[c * H_ + (k - IN)];
        g_wt[layer][k * G_ + c] = v;
    }
    if (k == 0) g_bias[layer][c] = bih[c] + bhh[c];
}

// ---------------- LSTM layer: one CTA = 32 batch rows, all 128 timesteps ----------------
// ext != nullptr -> read external x (B,T,IN); else read g_buf. Output always g_buf.
// In-place safe: within a timestep each CTA reads its x rows before writing its h rows,
// and CTAs own disjoint batch rows.
//
// Thread mapping (512 threads): cg = tid>>3 (cell-pair 0..63 -> cells c0=2*cg, gate stride H_),
//                               rg = tid&7  (row group 0..7 -> rows r0=4*rg .. r0+3)
// Per-thread accumulators: acc[4 rows][4 gates] of f32x2 over the cell pair (32 regs).
template <int IN>
__global__ void __launch_bounds__(NTHR, 1)
lstm_layer_kernel(const float* __restrict__ xext, int layer) {
    constexpr int K  = ((IN + H_) + KC_ - 1) / KC_ * KC_;  // 160 or 256
    constexpr int NC = K / KC_;

    const float* x_in  = (xext != nullptr) ? xext : g_buf;
    float*       h_out = g_buf;
    const float* Wt    = g_wt[layer];
    const float* bias  = g_bias[layer];

    extern __shared__ float smem[];
    float*  wbuf = smem;                           // 2 * KC_ * G_ floats (128 KB)
    float2* u2   = (float2*)(smem + 2 * KC_ * G_); // K * M_ duplicated [x;h] values

    const int tid = threadIdx.x;
    const int cg  = tid >> 3;        // 0..63 -> cell pair
    const int rg  = tid & 7;         // 0..7  -> row group
    const int c0  = cg * 2;
    const int r0  = rg * 4;
    const int b0  = blockIdx.x * M_;

    // zero u2 (covers h region for t=0 and pad region)
    for (int i = tid; i < K * M_; i += NTHR) u2[i] = make_float2(0.f, 0.f);

    // fused bias (per-thread cell pair, per gate)
    ull_t bias2[4];
    #pragma unroll
    for (int g = 0; g < 4; g++) {
        F2U b; b.f = *(const float2*)&bias[g * H_ + c0];
        bias2[g] = b.u;
    }
    ull_t acc[4][4];
    #pragma unroll
    for (int r = 0; r < 4; r++)
        #pragma unroll
        for (int g = 0; g < 4; g++) acc[r][g] = bias2[g];

    float cst[8];
    #pragma unroll
    for (int i = 0; i < 8; i++) cst[i] = 0.f;

    __syncthreads();

    // prefetch chunk 0 into buffer 0
    {
        const float4* s = (const float4*)(Wt);
        float4* d = (float4*)(wbuf);
        for (int i = tid; i < KC_ * G_ / 4; i += NTHR) cp16(d + i, s + i);
        CP_COMMIT();
    }

    // persistent parity: compute reads buffer (cc&1); prefetch targets ((cc+1)&1).
    // Always distinct, regardless of NC parity (NC=5 for layer 0!).
    int cc = 0;

    for (int t = 0; t < T_; t++) {
        // stage x_t (duplicated) into u2[0..IN)
        constexpr int IN4 = IN / 4;
        for (int i = tid; i < M_ * IN4; i += NTHR) {
            int r  = i / IN4;
            int kv = i - r * IN4;
            float4 v = *(const float4*)&x_in[((size_t)(b0 + r) * T_ + t) * IN + kv * 4];
            int kb = kv * 4;
            u2[(kb + 0) * M_ + r] = make_float2(v.x, v.x);
            u2[(kb + 1) * M_ + r] = make_float2(v.y, v.y);
            u2[(kb + 2) * M_ + r] = make_float2(v.z, v.z);
            u2[(kb + 3) * M_ + r] = make_float2(v.w, v.w);
        }

        for (int c = 0; c < NC; c++, cc++) {
            __syncthreads();  // staging done; prior chunk compute done reading its buffer
            {   // prefetch next chunk (wraps to chunk 0 for next t — weights static, valid)
                int cn = c + 1; if (cn == NC) cn = 0;
                const float4* s = (const float4*)(Wt + (size_t)cn * KC_ * G_);
                float4* d = (float4*)(wbuf + ((cc + 1) & 1) * (KC_ * G_));
                for (int i = tid; i < KC_ * G_ / 4; i += NTHR) cp16(d + i, s + i);
                CP_COMMIT();
            }
            CP_WAIT1();       // chunk c (committed one round earlier) has landed
            __syncthreads();  // make all threads' copies visible

            const float* wb = wbuf + (cc & 1) * (KC_ * G_);
            const int kbase = c * KC_;
            #pragma unroll 8
            for (int k = 0; k < KC_; k++) {
                const float* wr = wb + k * G_;
                ull_t wi = *(const ull_t*)(wr + 0 * H_ + c0);
                ull_t wf = *(const ull_t*)(wr + 1 * H_ + c0);
                ull_t wg = *(const ull_t*)(wr + 2 * H_ + c0);
                ull_t wo = *(const ull_t*)(wr + 3 * H_ + c0);
                const ull_t* ur = (const ull_t*)(u2 + (kbase + k) * M_ + r0);
                #pragma unroll
                for (int r = 0; r < 4; r++) {
                    ull_t uu = ur[r];
                    FMA2(acc[r][0], uu, wi);
                    FMA2(acc[r][1], uu, wf);
                    FMA2(acc[r][2], uu, wg);
                    FMA2(acc[r][3], uu, wo);
                }
            }
        }
        __syncthreads();  // all GEMM reads of u2 done before h updates

        // gates + state update + write-back
        #pragma unroll
        for (int r = 0; r < 4; r++) {
            F2U ai, af, ag, ao;
            ai.u = acc[r][0]; af.u = acc[r][1]; ag.u = acc[r][2]; ao.u = acc[r][3];

            float cn0 = sigm(af.f.x) * cst[2 * r + 0] + sigm(ai.f.x) * tanha(ag.f.x);
            float cn1 = sigm(af.f.y) * cst[2 * r + 1] + sigm(ai.f.y) * tanha(ag.f.y);
            cst[2 * r + 0] = cn0;
            cst[2 * r + 1] = cn1;
            float h0 = sigm(ao.f.x) * tanha(cn0);
            float h1 = sigm(ao.f.y) * tanha(cn1);

            int row = r0 + r;
            u2[(IN + c0 + 0) * M_ + row] = make_float2(h0, h0);
            u2[(IN + c0 + 1) * M_ + row] = make_float2(h1, h1);
            *(float2*)&h_out[((size_t)(b0 + row) * T_ + t) * H_ + c0] = make_float2(h0, h1);

            acc[r][0] = bias2[0]; acc[r][1] = bias2[1];
            acc[r][2] = bias2[2]; acc[r][3] = bias2[3];
        }
    }
}

// ---------------- FC head: out[b] = fc2( relu( fc1( h[b, T-1, :] ) ) ) ----------------
__global__ void fc_kernel(const float* __restrict__ w1, const float* __restrict__ b1,
                          const float* __restrict__ w2, const float* __restrict__ b2,
                          float* __restrict__ out) {
    __shared__ float hsh[H_];
    __shared__ float red[4];
    int b = blockIdx.x;
    int tid = threadIdx.x;  // 128 threads

    hsh[tid] = g_buf[((size_t)b * T_ + (T_ - 1)) * H_ + tid];
    __syncthreads();

    float partial = 0.f;
    if (tid < 64) {
        float d = b1[tid];
        const float* wr = w1 + tid * H_;
        #pragma unroll 8
        for (int k = 0; k < H_; k++) d += wr[k] * hsh[k];
        partial = fmaxf(d, 0.f) * w2[tid];
    }
    #pragma unroll
    for (int off = 16; off > 0; off >>= 1)
        partial += __shfl_down_sync(0xffffffff, partial, off);
    if ((tid & 31) == 0) red[tid >> 5] = partial;
    __syncthreads();
    if (tid == 0) out[b] = red[0] + red[1] + b2[0];
}

// ---------------- launch ----------------
extern "C" void kernel_launch(void* const* d_in, const int* in_sizes, int n_in,
                              void* d_out, int out_size) {
    const float* x     = (const float*)d_in[0];
    const float* wih0  = (const float*)d_in[1];
    const float* whh0  = (const float*)d_in[2];
    const float* bih0  = (const float*)d_in[3];
    const float* bhh0  = (const float*)d_in[4];
    const float* wih1  = (const float*)d_in[5];
    const float* whh1  = (const float*)d_in[6];
    const float* bih1  = (const float*)d_in[7];
    const float* bhh1  = (const float*)d_in[8];
    const float* wih2  = (const float*)d_in[9];
    const float* whh2  = (const float*)d_in[10];
    const float* bih2  = (const float*)d_in[11];
    const float* bhh2  = (const float*)d_in[12];
    const float* fc1w  = (const float*)d_in[13];
    const float* fc1b  = (const float*)d_in[14];
    const float* fc2w  = (const float*)d_in[15];
    const float* fc2b  = (const float*)d_in[16];

    const int SM8   = 2 * KC_ * G_ * 4 + 160 * M_ * 8;  // 172032
    const int SM128 = 2 * KC_ * G_ * 4 + 256 * M_ * 8;  // 196608
    cudaFuncSetAttribute(lstm_layer_kernel<8>,   cudaFuncAttributeMaxDynamicSharedMemorySize, SM8);
    cudaFuncSetAttribute(lstm_layer_kernel<128>, cudaFuncAttributeMaxDynamicSharedMemorySize, SM128);

    prep_kernel<<<256, 512>>>(wih0, whh0, bih0, bhh0, 0, 8);
    prep_kernel<<<256, 512>>>(wih1, whh1, bih1, bhh1, 1, 128);
    prep_kernel<<<256, 512>>>(wih2, whh2, bih2, bhh2, 2, 128);

    lstm_layer_kernel<8>  <<<B_ / M_, NTHR, SM8  >>>(x,       0);  // x   -> buf
    lstm_layer_kernel<128><<<B_ / M_, NTHR, SM128>>>(nullptr, 1);  // buf -> buf (in-place)
    lstm_layer_kernel<128><<<B_ / M_, NTHR, SM128>>>(nullptr, 2);  // buf -> buf (in-place)

    fc_kernel<<<B_, 128>>>(fc1w, fc1b, fc2w, fc2b, (float*)d_out);
}

// round 5
// speedup vs baseline: 1.6984x; 1.6984x over previous
#include <cuda_runtime.h>
#include <cstdint>

#define B_   4096
#define T_   128
#define H_   128
#define G_   512   // 4*H
#define M_   32    // batch rows per CTA
#define KC_  32    // K-chunk staged per cp.async round
#define NTHR 256

typedef unsigned long long ull_t;

// ---------------- scratch (device globals; no runtime allocation) ----------------
__device__ float g_buf[(size_t)B_ * T_ * H_];    // 256 MB, layers run in-place
// W layout per k (512 floats): [plane0: 64 pairs x (wi0,wi1,wf0,wf1)][plane1: 64 pairs x (wg0,wg1,wo0,wo1)]
__device__ float g_wt[3][256 * G_];
__device__ float g_bias[3][G_];                  // b_ih + b_hh (gate-major, unchanged)

// ---------------- small helpers ----------------
__device__ __forceinline__ float tanha(float x) {
    float r; asm("tanh.approx.f32 %0, %1;" : "=f"(r) : "f"(x)); return r;
}
__device__ __forceinline__ float sigm(float x) {
    return 0.5f * tanha(0.5f * x) + 0.5f;
}
__device__ __forceinline__ ull_t dup2(float v) {
    ull_t r; asm("mov.b64 %0, {%1, %1};" : "=l"(r) : "f"(v)); return r;
}

#define FMA2(acc, a, b) asm("fma.rn.f32x2 %0, %1, %2, %3;" : "=l"(acc) : "l"(a), "l"(b), "l"(acc))

__device__ __forceinline__ void cp16(void* smem_dst, const void* gsrc) {
    unsigned sa = (unsigned)__cvta_generic_to_shared(smem_dst);
    asm volatile("cp.async.cg.shared.global [%0], [%1], 16;" :: "r"(sa), "l"(gsrc));
}
#define CP_COMMIT() asm volatile("cp.async.commit_group;")
#define CP_WAIT1()  asm volatile("cp.async.wait_group 1;")

union F2U { float2 f; ull_t u; };

// ---------------- prep: build K-major repacked weight planes + fused bias ----------------
__global__ void prep_kernel(const float* __restrict__ wih, const float* __restrict__ whh,
                            const float* __restrict__ bih, const float* __restrict__ bhh,
                            int layer, int IN) {
    int k = blockIdx.x;          // 0..255
    int c = threadIdx.x;         // 0..511 : original row = gate g * 128 + cell
    int Kpad = ((IN + H_) + KC_ - 1) / KC_ * KC_;
    if (k < Kpad) {
        float v = 0.0f;
        if (k < IN)             v = wih[c * IN + k];
        else if (k < IN + H_)   v = whh[c * H_ + (k - IN)];
        int g    = c >> 7;       // gate 0..3
        int cell = c & 127;
        int pp   = cell >> 1;    // cell pair 0..63
        int e    = cell & 1;
        // plane = g>>1 (0: i,f ; 1: g,o), within-plane gate = g&1
        int idx = k * 512 + (g >> 1) * 256 + pp * 4 + (g & 1) * 2 + e;
        g_wt[layer][idx] = v;
    }
    if (k == 0) g_bias[layer][c] = bih[c] + bhh[c];
}

// ---------------- LSTM layer: one CTA = 32 batch rows, all 128 timesteps ----------------
// Thread map (256 thr): cg = tid>>2 (cell pair 0..63 -> cells c0=2cg, c0+1), rg = tid&3 -> rows r0=8*rg..+7.
// acc[8 rows][4 gates] f32x2 over the cell pair. u stored scalar [k][row]; dup in regs for FMA2.
template <int IN>
__global__ void __launch_bounds__(NTHR, 1)
lstm_layer_kernel(const float* __restrict__ xext, int layer) {
    constexpr int K  = ((IN + H_) + KC_ - 1) / KC_ * KC_;  // 160 or 256
    constexpr int NC = K / KC_;

    const float* x_in  = (xext != nullptr) ? xext : g_buf;
    float*       h_out = g_buf;
    const float* Wt    = g_wt[layer];
    const float* bias  = g_bias[layer];

    extern __shared__ float smem[];
    float* wbuf = smem;                       // 2 * KC_ * G_ floats (128 KB)
    float* u    = smem + 2 * KC_ * G_;        // K * M_ scalar [x;h] (<=32 KB)

    const int tid = threadIdx.x;
    const int cg  = tid >> 2;        // 0..63
    const int rg  = tid & 3;         // 0..3
    const int c0  = cg * 2;
    const int r0  = rg * 8;
    const int b0  = blockIdx.x * M_;

    for (int i = tid; i < K * M_; i += NTHR) u[i] = 0.f;

    ull_t bias2[4];
    #pragma unroll
    for (int g = 0; g < 4; g++) {
        F2U b; b.f = *(const float2*)&bias[g * H_ + c0];
        bias2[g] = b.u;
    }
    ull_t acc[8][4];
    #pragma unroll
    for (int r = 0; r < 8; r++)
        #pragma unroll
        for (int g = 0; g < 4; g++) acc[r][g] = bias2[g];

    float cst[16];
    #pragma unroll
    for (int i = 0; i < 16; i++) cst[i] = 0.f;

    __syncthreads();

    // prefetch chunk 0 into buffer 0
    {
        const float4* s = (const float4*)(Wt);
        float4* d = (float4*)(wbuf);
        for (int i = tid; i < KC_ * G_ / 4; i += NTHR) cp16(d + i, s + i);
        CP_COMMIT();
    }

    int cc = 0;  // persistent parity (NC may be odd: layer 0 NC=5)

    for (int t = 0; t < T_; t++) {
        // stage x_t (scalar) into u[0..IN)
        constexpr int IN4 = IN / 4;
        for (int i = tid; i < M_ * IN4; i += NTHR) {
            int r  = i / IN4;
            int kv = i - r * IN4;
            float4 v = *(const float4*)&x_in[((size_t)(b0 + r) * T_ + t) * IN + kv * 4];
            int kb = kv * 4;
            u[(kb + 0) * M_ + r] = v.x;
            u[(kb + 1) * M_ + r] = v.y;
            u[(kb + 2) * M_ + r] = v.z;
            u[(kb + 3) * M_ + r] = v.w;
        }

        for (int c = 0; c < NC; c++, cc++) {
            __syncthreads();  // staging done; prior chunk's reads of its wbuf done
            {   // prefetch next chunk into the other buffer
                int cn = c + 1; if (cn == NC) cn = 0;
                const float4* s = (const float4*)(Wt + (size_t)cn * KC_ * G_);
                float4* d = (float4*)(wbuf + ((cc + 1) & 1) * (KC_ * G_));
                for (int i = tid; i < KC_ * G_ / 4; i += NTHR) cp16(d + i, s + i);
                CP_COMMIT();
            }
            CP_WAIT1();       // chunk c landed
            __syncthreads();

            const float* wb = wbuf + (cc & 1) * (KC_ * G_);
            const int kbase = c * KC_;
            #pragma unroll 4
            for (int k = 0; k < KC_; k++) {
                const float* wr = wb + (k << 9);
                // plane0: (wi, wf) for this cell pair; plane1: (wg, wo)
                ulonglong2 wIF = *(const ulonglong2*)(wr + cg * 4);
                ulonglong2 wGO = *(const ulonglong2*)(wr + 256 + cg * 4);
                const float* urow = u + (kbase + k) * M_ + r0;
                float4 ua = *(const float4*)(urow);
                float4 ub = *(const float4*)(urow + 4);

                ull_t uu;
                uu = dup2(ua.x);
                FMA2(acc[0][0], uu, wIF.x); FMA2(acc[0][1], uu, wIF.y);
                FMA2(acc[0][2], uu, wGO.x); FMA2(acc[0][3], uu, wGO.y);
                uu = dup2(ua.y);
                FMA2(acc[1][0], uu, wIF.x); FMA2(acc[1][1], uu, wIF.y);
                FMA2(acc[1][2], uu, wGO.x); FMA2(acc[1][3], uu, wGO.y);
                uu = dup2(ua.z);
                FMA2(acc[2][0], uu, wIF.x); FMA2(acc[2][1], uu, wIF.y);
                FMA2(acc[2][2], uu, wGO.x); FMA2(acc[2][3], uu, wGO.y);
                uu = dup2(ua.w);
                FMA2(acc[3][0], uu, wIF.x); FMA2(acc[3][1], uu, wIF.y);
                FMA2(acc[3][2], uu, wGO.x); FMA2(acc[3][3], uu, wGO.y);
                uu = dup2(ub.x);
                FMA2(acc[4][0], uu, wIF.x); FMA2(acc[4][1], uu, wIF.y);
                FMA2(acc[4][2], uu, wGO.x); FMA2(acc[4][3], uu, wGO.y);
                uu = dup2(ub.y);
                FMA2(acc[5][0], uu, wIF.x); FMA2(acc[5][1], uu, wIF.y);
                FMA2(acc[5][2], uu, wGO.x); FMA2(acc[5][3], uu, wGO.y);
                uu = dup2(ub.z);
                FMA2(acc[6][0], uu, wIF.x); FMA2(acc[6][1], uu, wIF.y);
                FMA2(acc[6][2], uu, wGO.x); FMA2(acc[6][3], uu, wGO.y);
                uu = dup2(ub.w);
                FMA2(acc[7][0], uu, wIF.x); FMA2(acc[7][1], uu, wIF.y);
                FMA2(acc[7][2], uu, wGO.x); FMA2(acc[7][3], uu, wGO.y);
            }
        }
        __syncthreads();  // all GEMM reads of u done before h updates

        #pragma unroll
        for (int r = 0; r < 8; r++) {
            F2U ai, af, ag, ao;
            ai.u = acc[r][0]; af.u = acc[r][1]; ag.u = acc[r][2]; ao.u = acc[r][3];

            float cn0 = sigm(af.f.x) * cst[2 * r + 0] + sigm(ai.f.x) * tanha(ag.f.x);
            float cn1 = sigm(af.f.y) * cst[2 * r + 1] + sigm(ai.f.y) * tanha(ag.f.y);
            cst[2 * r + 0] = cn0;
            cst[2 * r + 1] = cn1;
            float h0 = sigm(ao.f.x) * tanha(cn0);
            float h1 = sigm(ao.f.y) * tanha(cn1);

            int row = r0 + r;
            u[(IN + c0 + 0) * M_ + row] = h0;
            u[(IN + c0 + 1) * M_ + row] = h1;
            *(float2*)&h_out[((size_t)(b0 + row) * T_ + t) * H_ + c0] = make_float2(h0, h1);

            acc[r][0] = bias2[0]; acc[r][1] = bias2[1];
            acc[r][2] = bias2[2]; acc[r][3] = bias2[3];
        }
    }
}

// ---------------- FC head ----------------
__global__ void fc_kernel(const float* __restrict__ w1, const float* __restrict__ b1,
                          const float* __restrict__ w2, const float* __restrict__ b2,
                          float* __restrict__ out) {
    __shared__ float hsh[H_];
    __shared__ float red[4];
    int b = blockIdx.x;
    int tid = threadIdx.x;  // 128 threads

    hsh[tid] = g_buf[((size_t)b * T_ + (T_ - 1)) * H_ + tid];
    __syncthreads();

    float partial = 0.f;
    if (tid < 64) {
        float d = b1[tid];
        const float* wr = w1 + tid * H_;
        #pragma unroll 8
        for (int k = 0; k < H_; k++) d += wr[k] * hsh[k];
        partial = fmaxf(d, 0.f) * w2[tid];
    }
    #pragma unroll
    for (int off = 16; off > 0; off >>= 1)
        partial += __shfl_down_sync(0xffffffff, partial, off);
    if ((tid & 31) == 0) red[tid >> 5] = partial;
    __syncthreads();
    if (tid == 0) out[b] = red[0] + red[1] + b2[0];
}

// ---------------- launch ----------------
extern "C" void kernel_launch(void* const* d_in, const int* in_sizes, int n_in,
                              void* d_out, int out_size) {
    const float* x     = (const float*)d_in[0];
    const float* wih0  = (const float*)d_in[1];
    const float* whh0  = (const float*)d_in[2];
    const float* bih0  = (const float*)d_in[3];
    const float* bhh0  = (const float*)d_in[4];
    const float* wih1  = (const float*)d_in[5];
    const float* whh1  = (const float*)d_in[6];
    const float* bih1  = (const float*)d_in[7];
    const float* bhh1  = (const float*)d_in[8];
    const float* wih2  = (const float*)d_in[9];
    const float* whh2  = (const float*)d_in[10];
    const float* bih2  = (const float*)d_in[11];
    const float* bhh2  = (const float*)d_in[12];
    const float* fc1w  = (const float*)d_in[13];
    const float* fc1b  = (const float*)d_in[14];
    const float* fc2w  = (const float*)d_in[15];
    const float* fc2b  = (const float*)d_in[16];

    const int SM8   = 2 * KC_ * G_ * 4 + 160 * M_ * 4;  // 131072 + 20480 = 151552
    const int SM128 = 2 * KC_ * G_ * 4 + 256 * M_ * 4;  // 131072 + 32768 = 163840
    cudaFuncSetAttribute(lstm_layer_kernel<8>,   cudaFuncAttributeMaxDynamicSharedMemorySize, SM8);
    cudaFuncSetAttribute(lstm_layer_kernel<128>, cudaFuncAttributeMaxDynamicSharedMemorySize, SM128);

    prep_kernel<<<256, 512>>>(wih0, whh0, bih0, bhh0, 0, 8);
    prep_kernel<<<256, 512>>>(wih1, whh1, bih1, bhh1, 1, 128);
    prep_kernel<<<256, 512>>>(wih2, whh2, bih2, bhh2, 2, 128);

    lstm_layer_kernel<8>  <<<B_ / M_, NTHR, SM8  >>>(x,       0);  // x   -> buf
    lstm_layer_kernel<128><<<B_ / M_, NTHR, SM128>>>(nullptr, 1);  // buf -> buf (in-place)
    lstm_layer_kernel<128><<<B_ / M_, NTHR, SM128>>>(nullptr, 2);  // buf -> buf (in-place)

    fc_kernel<<<B_, 128>>>(fc1w, fc1b, fc2w, fc2b, (float*)d_out);
}

// round 6
// speedup vs baseline: 1.7564x; 1.0342x over previous
#include <cuda_runtime.h>
#include <cstdint>

#define B_   4096
#define T_   128
#define H_   128
#define G_   512   // 4*H
#define M_   32    // batch rows per CTA
#define KC_  32    // K-chunk staged per cp.async round
#define NTHR 512   // 16 warps, 4/SMSP — R5 layout is LSU-light enough to feed them

typedef unsigned long long ull_t;

// ---------------- scratch (device globals; no runtime allocation) ----------------
__device__ float g_buf[(size_t)B_ * T_ * H_];    // 256 MB, layers run in-place
// W layout per k (512 floats): [plane0: 64 pairs x (wi0,wi1,wf0,wf1)][plane1: 64 pairs x (wg0,wg1,wo0,wo1)]
__device__ float g_wt[3][256 * G_];
__device__ float g_bias[3][G_];                  // b_ih + b_hh (gate-major)

// ---------------- small helpers ----------------
__device__ __forceinline__ float tanha(float x) {
    float r; asm("tanh.approx.f32 %0, %1;" : "=f"(r) : "f"(x)); return r;
}
__device__ __forceinline__ float sigm(float x) {
    return 0.5f * tanha(0.5f * x) + 0.5f;
}
__device__ __forceinline__ ull_t dup2(float v) {
    ull_t r; asm("mov.b64 %0, {%1, %1};" : "=l"(r) : "f"(v)); return r;
}

#define FMA2(acc, a, b) asm("fma.rn.f32x2 %0, %1, %2, %3;" : "=l"(acc) : "l"(a), "l"(b), "l"(acc))

__device__ __forceinline__ void cp16(void* smem_dst, const void* gsrc) {
    unsigned sa = (unsigned)__cvta_generic_to_shared(smem_dst);
    asm volatile("cp.async.cg.shared.global [%0], [%1], 16;" :: "r"(sa), "l"(gsrc));
}
#define CP_COMMIT() asm volatile("cp.async.commit_group;")
#define CP_WAIT1()  asm volatile("cp.async.wait_group 1;")

union F2U { float2 f; ull_t u; };

// ---------------- prep: build K-major repacked weight planes + fused bias ----------------
__global__ void prep_kernel(const float* __restrict__ wih, const float* __restrict__ whh,
                            const float* __restrict__ bih, const float* __restrict__ bhh,
                            int layer, int IN) {
    int k = blockIdx.x;          // 0..255
    int c = threadIdx.x;         // 0..511 : original row = gate g * 128 + cell
    int Kpad = ((IN + H_) + KC_ - 1) / KC_ * KC_;
    if (k < Kpad) {
        float v = 0.0f;
        if (k < IN)             v = wih[c * IN + k];
        else if (k < IN + H_)   v = whh[c * H_ + (k - IN)];
        int g    = c >> 7;       // gate 0..3
        int cell = c & 127;
        int pp   = cell >> 1;    // cell pair 0..63
        int e    = cell & 1;
        int idx = k * 512 + (g >> 1) * 256 + pp * 4 + (g & 1) * 2 + e;
        g_wt[layer][idx] = v;
    }
    if (k == 0) g_bias[layer][c] = bih[c] + bhh[c];
}

// ---------------- LSTM layer: one CTA = 32 batch rows, all 128 timesteps ----------------
// Thread map (512 thr): cg = tid>>3 (cell pair 0..63 -> cells c0=2cg, c0+1),
//                       rg = tid&7  (rows r0=4*rg .. r0+3)
// acc[4 rows][4 gates] f32x2 over the cell pair. u scalar [k][row]; dup in regs for FMA2.
template <int IN>
__global__ void __launch_bounds__(NTHR, 1)
lstm_layer_kernel(const float* __restrict__ xext, int layer) {
    constexpr int K  = ((IN + H_) + KC_ - 1) / KC_ * KC_;  // 160 or 256
    constexpr int NC = K / KC_;

    const float* x_in  = (xext != nullptr) ? xext : g_buf;
    float*       h_out = g_buf;
    const float* Wt    = g_wt[layer];
    const float* bias  = g_bias[layer];

    extern __shared__ float smem[];
    float* wbuf = smem;                       // 2 * KC_ * G_ floats (128 KB)
    float* u    = smem + 2 * KC_ * G_;        // K * M_ scalar [x;h] (<=32 KB)

    const int tid = threadIdx.x;
    const int cg  = tid >> 3;        // 0..63
    const int rg  = tid & 7;         // 0..7
    const int c0  = cg * 2;
    const int r0  = rg * 4;
    const int b0  = blockIdx.x * M_;

    for (int i = tid; i < K * M_; i += NTHR) u[i] = 0.f;

    ull_t bias2[4];
    #pragma unroll
    for (int g = 0; g < 4; g++) {
        F2U b; b.f = *(const float2*)&bias[g * H_ + c0];
        bias2[g] = b.u;
    }
    ull_t acc[4][4];
    #pragma unroll
    for (int r = 0; r < 4; r++)
        #pragma unroll
        for (int g = 0; g < 4; g++) acc[r][g] = bias2[g];

    float cst[8];
    #pragma unroll
    for (int i = 0; i < 8; i++) cst[i] = 0.f;

    __syncthreads();

    // prefetch chunk 0 into buffer 0
    {
        const float4* s = (const float4*)(Wt);
        float4* d = (float4*)(wbuf);
        for (int i = tid; i < KC_ * G_ / 4; i += NTHR) cp16(d + i, s + i);
        CP_COMMIT();
    }

    int cc = 0;  // persistent parity (NC may be odd: layer 0 NC=5)

    for (int t = 0; t < T_; t++) {
        // stage x_t (scalar) into u[0..IN)
        constexpr int IN4 = IN / 4;
        for (int i = tid; i < M_ * IN4; i += NTHR) {
            int r  = i / IN4;
            int kv = i - r * IN4;
            float4 v = *(const float4*)&x_in[((size_t)(b0 + r) * T_ + t) * IN + kv * 4];
            int kb = kv * 4;
            u[(kb + 0) * M_ + r] = v.x;
            u[(kb + 1) * M_ + r] = v.y;
            u[(kb + 2) * M_ + r] = v.z;
            u[(kb + 3) * M_ + r] = v.w;
        }

        for (int c = 0; c < NC; c++, cc++) {
            __syncthreads();  // staging done; chunk c-1 compute done reading buf (cc+1)&1
            {   // prefetch next chunk into the other buffer
                int cn = c + 1; if (cn == NC) cn = 0;
                const float4* s = (const float4*)(Wt + (size_t)cn * KC_ * G_);
                float4* d = (float4*)(wbuf + ((cc + 1) & 1) * (KC_ * G_));
                for (int i = tid; i < KC_ * G_ / 4; i += NTHR) cp16(d + i, s + i);
                CP_COMMIT();
            }
            CP_WAIT1();       // chunk c landed
            __syncthreads();

            const float* wb = wbuf + (cc & 1) * (KC_ * G_);
            const int kbase = c * KC_;
            #pragma unroll 8
            for (int k = 0; k < KC_; k++) {
                const float* wr = wb + (k << 9);
                ulonglong2 wIF = *(const ulonglong2*)(wr + cg * 4);        // (wi, wf)
                ulonglong2 wGO = *(const ulonglong2*)(wr + 256 + cg * 4);  // (wg, wo)
                float4 ua = *(const float4*)(u + (kbase + k) * M_ + r0);

                ull_t uu;
                uu = dup2(ua.x);
                FMA2(acc[0][0], uu, wIF.x); FMA2(acc[0][1], uu, wIF.y);
                FMA2(acc[0][2], uu, wGO.x); FMA2(acc[0][3], uu, wGO.y);
                uu = dup2(ua.y);
                FMA2(acc[1][0], uu, wIF.x); FMA2(acc[1][1], uu, wIF.y);
                FMA2(acc[1][2], uu, wGO.x); FMA2(acc[1][3], uu, wGO.y);
                uu = dup2(ua.z);
                FMA2(acc[2][0], uu, wIF.x); FMA2(acc[2][1], uu, wIF.y);
                FMA2(acc[2][2], uu, wGO.x); FMA2(acc[2][3], uu, wGO.y);
                uu = dup2(ua.w);
                FMA2(acc[3][0], uu, wIF.x); FMA2(acc[3][1], uu, wIF.y);
                FMA2(acc[3][2], uu, wGO.x); FMA2(acc[3][3], uu, wGO.y);
            }
        }
        __syncthreads();  // all GEMM reads of u done before h updates

        #pragma unroll
        for (int r = 0; r < 4; r++) {
            F2U ai, af, ag, ao;
            ai.u = acc[r][0]; af.u = acc[r][1]; ag.u = acc[r][2]; ao.u = acc[r][3];

            float cn0 = sigm(af.f.x) * cst[2 * r + 0] + sigm(ai.f.x) * tanha(ag.f.x);
            float cn1 = sigm(af.f.y) * cst[2 * r + 1] + sigm(ai.f.y) * tanha(ag.f.y);
            cst[2 * r + 0] = cn0;
            cst[2 * r + 1] = cn1;
            float h0 = sigm(ao.f.x) * tanha(cn0);
            float h1 = sigm(ao.f.y) * tanha(cn1);

            int row = r0 + r;
            u[(IN + c0 + 0) * M_ + row] = h0;
            u[(IN + c0 + 1) * M_ + row] = h1;
            *(float2*)&h_out[((size_t)(b0 + row) * T_ + t) * H_ + c0] = make_float2(h0, h1);

            acc[r][0] = bias2[0]; acc[r][1] = bias2[1];
            acc[r][2] = bias2[2]; acc[r][3] = bias2[3];
        }
    }
}

// ---------------- FC head ----------------
__global__ void fc_kernel(const float* __restrict__ w1, const float* __restrict__ b1,
                          const float* __restrict__ w2, const float* __restrict__ b2,
                          float* __restrict__ out) {
    __shared__ float hsh[H_];
    __shared__ float red[4];
    int b = blockIdx.x;
    int tid = threadIdx.x;  // 128 threads

    hsh[tid] = g_buf[((size_t)b * T_ + (T_ - 1)) * H_ + tid];
    __syncthreads();

    float partial = 0.f;
    if (tid < 64) {
        float d = b1[tid];
        const float* wr = w1 + tid * H_;
        #pragma unroll 8
        for (int k = 0; k < H_; k++) d += wr[k] * hsh[k];
        partial = fmaxf(d, 0.f) * w2[tid];
    }
    #pragma unroll
    for (int off = 16; off > 0; off >>= 1)
        partial += __shfl_down_sync(0xffffffff, partial, off);
    if ((tid & 31) == 0) red[tid >> 5] = partial;
    __syncthreads();
    if (tid == 0) out[b] = red[0] + red[1] + b2[0];
}

// ---------------- launch ----------------
extern "C" void kernel_launch(void* const* d_in, const int* in_sizes, int n_in,
                              void* d_out, int out_size) {
    const float* x     = (const float*)d_in[0];
    const float* wih0  = (const float*)d_in[1];
    const float* whh0  = (const float*)d_in[2];
    const float* bih0  = (const float*)d_in[3];
    const float* bhh0  = (const float*)d_in[4];
    const float* wih1  = (const float*)d_in[5];
    const float* whh1  = (const float*)d_in[6];
    const float* bih1  = (const float*)d_in[7];
    const float* bhh1  = (const float*)d_in[8];
    const float* wih2  = (const float*)d_in[9];
    const float* whh2  = (const float*)d_in[10];
    const float* bih2  = (const float*)d_in[11];
    const float* bhh2  = (const float*)d_in[12];
    const float* fc1w  = (const float*)d_in[13];
    const float* fc1b  = (const float*)d_in[14];
    const float* fc2w  = (const float*)d_in[15];
    const float* fc2b  = (const float*)d_in[16];

    const int SM8   = 2 * KC_ * G_ * 4 + 160 * M_ * 4;  // 151552
    const int SM128 = 2 * KC_ * G_ * 4 + 256 * M_ * 4;  // 163840
    cudaFuncSetAttribute(lstm_layer_kernel<8>,   cudaFuncAttributeMaxDynamicSharedMemorySize, SM8);
    cudaFuncSetAttribute(lstm_layer_kernel<128>, cudaFuncAttributeMaxDynamicSharedMemorySize, SM128);

    prep_kernel<<<256, 512>>>(wih0, whh0, bih0, bhh0, 0, 8);
    prep_kernel<<<256, 512>>>(wih1, whh1, bih1, bhh1, 1, 128);
    prep_kernel<<<256, 512>>>(wih2, whh2, bih2, bhh2, 2, 128);

    lstm_layer_kernel<8>  <<<B_ / M_, NTHR, SM8  >>>(x,       0);  // x   -> buf
    lstm_layer_kernel<128><<<B_ / M_, NTHR, SM128>>>(nullptr, 1);  // buf -> buf (in-place)
    lstm_layer_kernel<128><<<B_ / M_, NTHR, SM128>>>(nullptr, 2);  // buf -> buf (in-place)

    fc_kernel<<<B_, 128>>>(fc1w, fc1b, fc2w, fc2b, (float*)d_out);
}

// round 8
// speedup vs baseline: 4.1236x; 2.3477x over previous
#include <cuda_runtime.h>
#include <cuda_bf16.h>
#include <cstdint>

#define B_   4096
#define T_   128
#define H_   128
#define G_   512
#define M_   32     // batch rows per CTA (MMA N)
#define NTHR 256    // 8 warps; warp w owns cells [w*16, w*16+16) x all 4 gates

// ---------------- device scratch ----------------
// Packed W image per layer: NC chunks of 64KB; chunk = [hi 32KB | lo 32KB];
// each half: 512 packed rows x 32 k bf16, ldmatrix-swizzled (seg ^= (p>>1)&3).
// Packed row p = (cell>>4)*64 + gate*16 + (cell&15)  => warp w m-tile m = gate m, cells w*16..+15.
__device__ __align__(1024) unsigned char g_wtA[3][8 * 65536];
__device__ float g_bias[3][G_];
__device__ float g_buf[(size_t)B_ * T_ * H_];   // fp32 activations, layers run in-place

// ---------------- helpers ----------------
__device__ __forceinline__ float tanha(float x) {
    float r; asm("tanh.approx.f32 %0, %1;" : "=f"(r) : "f"(x)); return r;
}
__device__ __forceinline__ float sigm(float x) { return 0.5f * tanha(0.5f * x) + 0.5f; }

union BU { __nv_bfloat162 h; uint32_t u; };
__device__ __forceinline__ uint32_t pack2(float a, float b) {
    BU v; v.h = __floats2bfloat162_rn(a, b); return v.u;
}
__device__ __forceinline__ float resid(float a) {
    return a - __bfloat162float(__float2bfloat16_rn(a));
}

#define HMMA(d, a, b) asm volatile( \
    "mma.sync.aligned.m16n8k16.row.col.f32.bf16.bf16.f32 " \
    "{%0,%1,%2,%3}, {%4,%5,%6,%7}, {%8,%9}, {%0,%1,%2,%3};" \
    : "+f"((d)[0]), "+f"((d)[1]), "+f"((d)[2]), "+f"((d)[3]) \
    : "r"((a)[0]), "r"((a)[1]), "r"((a)[2]), "r"((a)[3]), "r"((b)[0]), "r"((b)[1]))

#define LDSM4(r, addr) asm volatile( \
    "ldmatrix.sync.aligned.m8n8.x4.shared.b16 {%0,%1,%2,%3}, [%4];" \
    : "=r"((r)[0]), "=r"((r)[1]), "=r"((r)[2]), "=r"((r)[3]) : "r"(addr))

#define LDS32(r, addr) asm volatile("ld.shared.b32 %0, [%1];" : "=r"(r) : "r"(addr))

__device__ __forceinline__ void mbar_init(uint32_t a, uint32_t cnt) {
    asm volatile("mbarrier.init.shared.b64 [%0], %1;" :: "r"(a), "r"(cnt) : "memory");
}
__device__ __forceinline__ void mbar_expect(uint32_t a, uint32_t bytes) {
    asm volatile("mbarrier.arrive.expect_tx.shared::cta.b64 _, [%0], %1;"
                 :: "r"(a), "r"(bytes) : "memory");
}
__device__ __forceinline__ void mbar_wait(uint32_t a, uint32_t parity) {
    asm volatile(
        "{\n\t.reg .pred P;\n"
        "WL%=:\n\tmbarrier.try_wait.parity.shared::cta.b64 P, [%0], %1;\n"
        "\t@!P bra WL%=;\n\t}"
        :: "r"(a), "r"(parity) : "memory");
}
__device__ __forceinline__ void bulk_cp(uint32_t dst, const void* src, uint32_t bytes, uint32_t mbar) {
    asm volatile("cp.async.bulk.shared::cluster.global.mbarrier::complete_tx::bytes "
                 "[%0], [%1], %2, [%3];"
                 :: "r"(dst), "l"(src), "r"(bytes), "r"(mbar) : "memory");
}

// ---------------- prep: pack W (bf16 hi/lo) into ldmatrix-swizzled image ----------------
__global__ void prep_w(const float* __restrict__ wih, const float* __restrict__ whh,
                       int layer, int IN, int INP) {
    int k = blockIdx.x;           // 0..K-1
    int row = threadIdx.x;        // 0..511 = gate*128 + cell
    float v;
    if (k < INP) v = (k < IN) ? wih[row * IN + k] : 0.f;
    else         v = whh[row * H_ + (k - INP)];
    __nv_bfloat16 hi = __float2bfloat16_rn(v);
    __nv_bfloat16 lo = __float2bfloat16_rn(v - __bfloat162float(hi));
    int gate = row >> 7, cell = row & 127;
    unsigned p = ((cell >> 4) << 6) + (gate << 4) + (cell & 15);
    int chunk = k >> 5;
    unsigned kb = (unsigned)(k & 31) * 2;
    unsigned off = p * 64 + ((((kb >> 4) ^ ((p >> 1) & 3)) << 4) | (kb & 15));
    *(__nv_bfloat16*)&g_wtA[layer][chunk * 65536 + off]         = hi;
    *(__nv_bfloat16*)&g_wtA[layer][chunk * 65536 + 32768 + off] = lo;
}

__global__ void prep_bias(const float* __restrict__ bih, const float* __restrict__ bhh, int layer) {
    int c = threadIdx.x;
    g_bias[layer][c] = bih[c] + bhh[c];
}

// ---------------- LSTM layer via mma.sync bf16 (3-term split) ----------------
template <int IN, int INP, int NC>
__global__ void __launch_bounds__(NTHR, 1)
lstm_mma(const float* __restrict__ xext, int layer) {
    constexpr int K    = INP + H_;                       // 160 or 256
    constexpr int SROW = ((K * 2 + 127) / 128) * 128 + 16;  // bytes; ≡16 mod 128 (bank spread)

    const float* x_in = (xext != nullptr) ? xext : g_buf;
    extern __shared__ unsigned char smem[];
    uint32_t sb = (uint32_t)__cvta_generic_to_shared(smem);
    uint32_t s0 = (sb + 1023) & ~1023u;
    uint32_t MB = s0;                         // two mbarriers
    uint32_t A0 = s0 + 128;                   // 2 x 65536 W chunk buffers
    uint32_t U0 = A0 + 131072;                // u hi: 32 x SROW
    uint32_t U1 = U0 + 32 * SROW;             // u lo
    unsigned char* sp = smem + (s0 - sb);
    const unsigned UH = 128 + 131072;         // byte offset of U0 from s0
    const unsigned UL = UH + 32 * SROW;

    const int tid = threadIdx.x, wid = tid >> 5, lane = tid & 31;
    const int g = lane >> 2, t4 = lane & 3;
    const int b0 = blockIdx.x * M_;

    // zero u (h0 = 0, pad region stays 0 forever)
    for (int i = tid; i < (64 * SROW) / 4; i += NTHR) ((uint32_t*)(sp + UH))[i] = 0;

    if (tid == 0) { mbar_init(MB, 1); mbar_init(MB + 8, 1); }
    __syncthreads();
    if (tid == 0) {               // preload chunk 0 -> buffer 0
        mbar_expect(MB, 65536);
        bulk_cp(A0, g_wtA[layer], 65536, MB);
    }

    const int cell0 = wid * 16 + g;
    float bias_v[4][2];
    #pragma unroll
    for (int m = 0; m < 4; m++) {
        bias_v[m][0] = g_bias[layer][m * 128 + cell0];
        bias_v[m][1] = g_bias[layer][m * 128 + cell0 + 8];
    }
    float acc[4][4][4];
    #pragma unroll
    for (int m = 0; m < 4; m++)
        #pragma unroll
        for (int nt = 0; nt < 4; nt++) {
            acc[m][nt][0] = acc[m][nt][1] = bias_v[m][0];
            acc[m][nt][2] = acc[m][nt][3] = bias_v[m][1];
        }
    float cst[16];
    #pragma unroll
    for (int i = 0; i < 16; i++) cst[i] = 0.f;

    int ph0 = 0, ph1 = 0;
    int gc = 0;

    for (int t = 0; t < T_; t++) {
        // ---- stage x_t into u (bf16 hi/lo), rows = batch, cols = k ----
        constexpr int IN4 = IN / 4;
        for (int i = tid; i < M_ * IN4; i += NTHR) {
            int r  = i / IN4;
            int kv = i - r * IN4;
            float4 v = *(const float4*)&x_in[((size_t)(b0 + r) * T_ + t) * IN + kv * 4];
            unsigned off = (unsigned)r * SROW + kv * 8;
            *(uint32_t*)(sp + UH + off)     = pack2(v.x, v.y);
            *(uint32_t*)(sp + UH + off + 4) = pack2(v.z, v.w);
            *(uint32_t*)(sp + UL + off)     = pack2(resid(v.x), resid(v.y));
            *(uint32_t*)(sp + UL + off + 4) = pack2(resid(v.z), resid(v.w));
        }

        // ---- chunk loop ----
        for (int c = 0; c < NC; c++) {
            __syncthreads();  // staging + prev-chunk reads of target W buffer complete
            int cur = gc & 1;
            if (tid == 0 && !(t == T_ - 1 && c == NC - 1)) {
                int cn = (c + 1 == NC) ? 0 : c + 1;   // weights t-invariant; wrap valid
                mbar_expect(MB + (cur ^ 1) * 8, 65536);
                bulk_cp(A0 + (cur ^ 1) * 65536, g_wtA[layer] + (size_t)cn * 65536,
                        65536, MB + (cur ^ 1) * 8);
            }
            if (cur == 0) { mbar_wait(MB, ph0);     ph0 ^= 1; }
            else          { mbar_wait(MB + 8, ph1); ph1 ^= 1; }

            uint32_t Ah = A0 + (unsigned)cur * 65536;
            uint32_t Al = Ah + 32768;
            #pragma unroll
            for (int ks = 0; ks < 2; ks++) {
                const int kb = c * 32 + ks * 16;
                // B fragments (direct LDS.32; u stored [n][k])
                uint32_t bh[4][2], bl[4][2];
                #pragma unroll
                for (int nt = 0; nt < 4; nt++) {
                    uint32_t uoff = (uint32_t)(nt * 8 + g) * SROW + (kb + 2 * t4) * 2;
                    LDS32(bh[nt][0], U0 + uoff); LDS32(bh[nt][1], U0 + uoff + 16);
                    LDS32(bl[nt][0], U1 + uoff); LDS32(bl[nt][1], U1 + uoff + 16);
                }
                // A fragments via swizzled ldmatrix.x4
                unsigned p0  = (unsigned)wid * 64 + (lane & 15);
                unsigned seg = ((unsigned)(ks * 2 + (lane >> 4))) ^ ((p0 >> 1) & 3);
                uint32_t ab  = p0 * 64 + seg * 16;
                #pragma unroll
                for (int m = 0; m < 4; m++) {
                    uint32_t ah[4], al[4];
                    LDSM4(ah, Ah + ab + m * 1024);
                    LDSM4(al, Al + ab + m * 1024);
                    #pragma unroll
                    for (int nt = 0; nt < 4; nt++) {
                        HMMA(acc[m][nt], ah, bh[nt]);   // Whi*Uhi
                        HMMA(acc[m][nt], ah, bl[nt]);   // Whi*Ulo
                        HMMA(acc[m][nt], al, bh[nt]);   // Wlo*Uhi
                    }
                }
            }
            gc++;
        }
        __syncthreads();  // all MMA reads of u done before h writes

        // ---- epilogue: gates from registers, state update, h write-back ----
        #pragma unroll
        for (int ci = 0; ci < 2; ci++)
            #pragma unroll
            for (int nt = 0; nt < 4; nt++)
                #pragma unroll
                for (int par = 0; par < 2; par++) {
                    int e = ci * 2 + par;
                    float vi = acc[0][nt][e], vf = acc[1][nt][e];
                    float vg = acc[2][nt][e], vo = acc[3][nt][e];
                    int sidx = ci * 8 + nt * 2 + par;
                    float cn = sigm(vf) * cst[sidx] + sigm(vi) * tanha(vg);
                    cst[sidx] = cn;
                    float h = sigm(vo) * tanha(cn);
                    int cell = cell0 + ci * 8;
                    int b    = nt * 8 + t4 * 2 + par;
                    g_buf[((size_t)(b0 + b) * T_ + t) * H_ + cell] = h;
                    __nv_bfloat16 hh = __float2bfloat16_rn(h);
                    __nv_bfloat16 hl = __float2bfloat16_rn(h - __bfloat162float(hh));
                    unsigned ho = (unsigned)b * SROW + (INP + cell) * 2;
                    *(__nv_bfloat16*)(sp + UH + ho) = hh;
                    *(__nv_bfloat16*)(sp + UL + ho) = hl;
                }
        // reset accumulators to bias
        #pragma unroll
        for (int m = 0; m < 4; m++)
            #pragma unroll
            for (int nt = 0; nt < 4; nt++) {
                acc[m][nt][0] = acc[m][nt][1] = bias_v[m][0];
                acc[m][nt][2] = acc[m][nt][3] = bias_v[m][1];
            }
    }
}

// ---------------- FC head ----------------
__global__ void fc_kernel(const float* __restrict__ w1, const float* __restrict__ b1,
                          const float* __restrict__ w2, const float* __restrict__ b2,
                          float* __restrict__ out) {
    __shared__ float hsh[H_];
    __shared__ float red[4];
    int b = blockIdx.x;
    int tid = threadIdx.x;  // 128 threads

    hsh[tid] = g_buf[((size_t)b * T_ + (T_ - 1)) * H_ + tid];
    __syncthreads();

    float partial = 0.f;
    if (tid < 64) {
        float d = b1[tid];
        const float* wr = w1 + tid * H_;
        #pragma unroll 8
        for (int k = 0; k < H_; k++) d += wr[k] * hsh[k];
        partial = fmaxf(d, 0.f) * w2[tid];
    }
    #pragma unroll
    for (int off = 16; off > 0; off >>= 1)
        partial += __shfl_down_sync(0xffffffff, partial, off);
    if ((tid & 31) == 0) red[tid >> 5] = partial;
    __syncthreads();
    if (tid == 0) out[b] = red[0] + red[1] + b2[0];
}

// ---------------- launch ----------------
extern "C" void kernel_launch(void* const* d_in, const int* in_sizes, int n_in,
                              void* d_out, int out_size) {
    const float* x     = (const float*)d_in[0];
    const float* wih0  = (const float*)d_in[1];
    const float* whh0  = (const float*)d_in[2];
    const float* bih0  = (const float*)d_in[3];
    const float* bhh0  = (const float*)d_in[4];
    const float* wih1  = (const float*)d_in[5];
    const float* whh1  = (const float*)d_in[6];
    const float* bih1  = (const float*)d_in[7];
    const float* bhh1  = (const float*)d_in[8];
    const float* wih2  = (const float*)d_in[9];
    const float* whh2  = (const float*)d_in[10];
    const float* bih2  = (const float*)d_in[11];
    const float* bhh2  = (const float*)d_in[12];
    const float* fc1w  = (const float*)d_in[13];
    const float* fc1b  = (const float*)d_in[14];
    const float* fc2w  = (const float*)d_in[15];
    const float* fc2b  = (const float*)d_in[16];

    // dyn smem: 1024 align slack + 128 hdr + 131072 W + 64*SROW u
    const int SM5 = 1024 + 128 + 131072 + 64 * 400;  // K=160: 157,752 -> round
    const int SM8 = 1024 + 128 + 131072 + 64 * 528;  // K=256: 165,984
    cudaFuncSetAttribute(lstm_mma<8, 32, 5>,    cudaFuncAttributeMaxDynamicSharedMemorySize, SM5);
    cudaFuncSetAttribute(lstm_mma<128, 128, 8>, cudaFuncAttributeMaxDynamicSharedMemorySize, SM8);

    prep_w<<<160, 512>>>(wih0, whh0, 0, 8,   32);
    prep_w<<<256, 512>>>(wih1, whh1, 1, 128, 128);
    prep_w<<<256, 512>>>(wih2, whh2, 2, 128, 128);
    prep_bias<<<1, 512>>>(bih0, bhh0, 0);
    prep_bias<<<1, 512>>>(bih1, bhh1, 1);
    prep_bias<<<1, 512>>>(bih2, bhh2, 2);

    lstm_mma<8, 32, 5>   <<<B_ / M_, NTHR, SM5>>>(x,       0);  // x   -> buf
    lstm_mma<128, 128, 8><<<B_ / M_, NTHR, SM8>>>(nullptr, 1);  // buf -> buf (in-place)
    lstm_mma<128, 128, 8><<<B_ / M_, NTHR, SM8>>>(nullptr, 2);  // buf -> buf (in-place)

    fc_kernel<<<B_, 128>>>(fc1w, fc1b, fc2w, fc2b, (float*)d_out);
}